// round 17
// baseline (speedup 1.0000x reference)
#include <cuda_runtime.h>
#include <cuda_fp16.h>
#include <cstdint>

// Shapes (fixed for this problem)
#define N_TOTAL (64 * 4096)      // 262144 nodes
#define NHID    128
#define NN      4096             // nodes per graph == w3 dim
#define MB      64               // batch (graphs)

// table for s(f,g), t(f,g): range [-6,6]^2, h = 3/32, 129x129 points
#define TAB_N    129
#define TAB_LO   (-6.0f)
#define TAB_INVH (32.0f / 3.0f)

// ---------------- scratch (device globals; no allocation allowed) ----------
__device__ __align__(16) float2 g_fd [N_TOTAL];   // {agg1, deg} interleaved
__device__ __align__(16) float g_s   [N_TOTAL];
__device__ __align__(16) float g_t   [N_TOTAL];
__device__ __align__(16) float g_agg2[N_TOTAL];
#define GEMM_KSPLIT 8
__device__ float g_part[GEMM_KSPLIT * N_TOTAL];        // split-K partials (8MB)
__device__ __align__(16) unsigned short g_Ah[N_TOTAL]; // A = fp16(h2)
__device__ __align__(16) float2 g_tab[TAB_N * TAB_N];  // {s,t} table (133KB)

#define C_2LOG2E 2.88539008177792681f   // 2*log2(e)

__device__ __forceinline__ float ex2f(float x) {
    float e; asm("ex2.approx.f32 %0, %1;" : "=f"(e) : "f"(x)); return e;
}
__device__ __forceinline__ float rcpf(float x) {
    float r; asm("rcp.approx.f32 %0, %1;" : "=f"(r) : "f"(x)); return r;
}
// tanh from prescaled xp = 2*log2e*x : tanh = 1 - 2/(exp2(xp)+1)
__device__ __forceinline__ float tanh_exp2(float xp) {
    return fmaf(-2.0f, rcpf(ex2f(xp) + 1.0f), 1.0f);
}

// pack two floats into one f16x2 register: {lo=a, hi=b}
__device__ __forceinline__ uint32_t pack_f16x2(float a, float b) {
    uint32_t d;
    asm("cvt.rn.f16x2.f32 %0, %1, %2;" : "=r"(d) : "f"(b), "f"(a));
    return d;
}

// ---------------- side-branch: build s/t table (footprint-light) ------------
__global__ void k_tab(const float* __restrict__ ws1, const float* __restrict__ wn1,
                      const float* __restrict__ b1,
                      const float* __restrict__ ws2, const float* __restrict__ wn2) {
    int p = blockIdx.x * blockDim.x + threadIdx.x;
    if (p >= TAB_N * TAB_N) return;
    int fi = p % TAB_N, gi = p / TAB_N;
    float f = TAB_LO + fi * (1.0f / TAB_INVH);
    float g = TAB_LO + gi * (1.0f / TAB_INVH);
    float s = 0.0f, t = 0.0f;
#pragma unroll 4
    for (int j = 0; j < NHID; j++) {
        float xp = C_2LOG2E * fmaf(f, __ldg(&ws1[j]),
                                   fmaf(g, __ldg(&wn1[j]), __ldg(&b1[j])));
        float r = tanh_exp2(xp);
        s = fmaf(r, __ldg(&ws2[j]), s);
        t = fmaf(r, __ldg(&wn2[j]), t);
    }
    g_tab[p] = make_float2(s, t);
}

// ---------------- kernel 0: zero {agg1,deg} only (agg2 zeroed in node1) -----
__global__ void k_zero(int n4) {   // n4 = N_TOTAL/4
    int i = blockIdx.x * blockDim.x + threadIdx.x;
    if (i < n4) {
        float4 z = make_float4(0.f, 0.f, 0.f, 0.f);
        reinterpret_cast<float4*>(g_fd)[2 * i]     = z;
        reinterpret_cast<float4*>(g_fd)[2 * i + 1] = z;
    }
}

// ---------------- kernel 1: edge scatter pass 1, 4 edges/thread -------------
__global__ void k_edge1(const float* __restrict__ feat,
                        const int* __restrict__ src,
                        const int* __restrict__ dst, int e4) {  // e4 = E/4
    int i = blockIdx.x * blockDim.x + threadIdx.x;
    if (i < e4) {
        int4 s4 = __ldg(&reinterpret_cast<const int4*>(src)[i]);
        int4 d4 = __ldg(&reinterpret_cast<const int4*>(dst)[i]);
        // 4 independent gathers in flight
        float v0 = __ldg(&feat[s4.x]);
        float v1 = __ldg(&feat[s4.y]);
        float v2 = __ldg(&feat[s4.z]);
        float v3 = __ldg(&feat[s4.w]);
        asm volatile("red.global.add.v2.f32 [%0], {%1, %2};"
                     :: "l"(g_fd + d4.x), "f"(v0), "f"(1.0f) : "memory");
        asm volatile("red.global.add.v2.f32 [%0], {%1, %2};"
                     :: "l"(g_fd + d4.y), "f"(v1), "f"(1.0f) : "memory");
        asm volatile("red.global.add.v2.f32 [%0], {%1, %2};"
                     :: "l"(g_fd + d4.z), "f"(v2), "f"(1.0f) : "memory");
        asm volatile("red.global.add.v2.f32 [%0], {%1, %2};"
                     :: "l"(g_fd + d4.w), "f"(v3), "f"(1.0f) : "memory");
    }
}

// ---------------- kernel 2: s,t via bicubic table lookup (R6 proven) --------
__device__ __forceinline__ void cubic_w(float x, float w[4]) {
    float xm1 = x - 1.0f, xm2 = x - 2.0f, xp1 = x + 1.0f;
    float a = xm1 * xm2;
    float b = xp1 * x;
    w[0] = -x * a * (1.0f / 6.0f);
    w[1] = xp1 * a * 0.5f;
    w[2] = -b * xm2 * 0.5f;
    w[3] = b * xm1 * (1.0f / 6.0f);
}

__global__ __launch_bounds__(256) void k_node1(const float* __restrict__ feat,
                                               int n_total) {
    int n = blockIdx.x * blockDim.x + threadIdx.x;
    if (n >= n_total) return;

    float f   = feat[n];
    float2 fd = g_fd[n];
    float g   = __fdividef(fd.x, fmaxf(fd.y, 1.0f));

    float u = fminf(fmaxf((f - TAB_LO) * TAB_INVH, 1.0f), (float)(TAB_N - 3) - 1e-3f);
    float v = fminf(fmaxf((g - TAB_LO) * TAB_INVH, 1.0f), (float)(TAB_N - 3) - 1e-3f);
    int iu = (int)u;  float x = u - iu;
    int iv = (int)v;  float y = v - iv;

    float wx[4], wy[4];
    cubic_w(x, wx);
    cubic_w(y, wy);

    const float2* base = g_tab + (iv - 1) * TAB_N + (iu - 1);
    float s = 0.0f, t = 0.0f;
#pragma unroll
    for (int a = 0; a < 4; a++) {
        const float2* row = base + a * TAB_N;
        float rs = 0.0f, rt = 0.0f;
#pragma unroll
        for (int b = 0; b < 4; b++) {
            float2 tv = __ldg(&row[b]);
            rs = fmaf(wx[b], tv.x, rs);
            rt = fmaf(wx[b], tv.y, rt);
        }
        s = fmaf(wy[a], rs, s);
        t = fmaf(wy[a], rt, t);
    }
    g_s[n] = s;
    g_t[n] = t;
    g_agg2[n] = 0.0f;   // zero for edge2 (runs after this kernel)
}

// ---------------- kernel 3: edge scatter pass 2, 4 edges/thread -------------
__global__ void k_edge2(const int* __restrict__ src,
                        const int* __restrict__ dst, int e4) {  // e4 = E/4
    int i = blockIdx.x * blockDim.x + threadIdx.x;
    if (i < e4) {
        int4 s4 = __ldg(&reinterpret_cast<const int4*>(src)[i]);
        int4 d4 = __ldg(&reinterpret_cast<const int4*>(dst)[i]);
        float v0 = __ldg(&g_t[s4.x]);
        float v1 = __ldg(&g_t[s4.y]);
        float v2 = __ldg(&g_t[s4.z]);
        float v3 = __ldg(&g_t[s4.w]);
        atomicAdd(&g_agg2[d4.x], v0);
        atomicAdd(&g_agg2[d4.y], v1);
        atomicAdd(&g_agg2[d4.z], v2);
        atomicAdd(&g_agg2[d4.w], v3);
    }
}

// ---------------- kernel 4: out1; A = fp16(tanh(out1)) ----------------------
__global__ void k_node2(const float* __restrict__ b2,
                        float* __restrict__ out, int n_total) {
    int n = blockIdx.x * blockDim.x + threadIdx.x;
    if (n < n_total) {
        float o = g_s[n] + __fdividef(g_agg2[n], fmaxf(g_fd[n].y, 1.0f)) + b2[0];
        out[n] = o;                          // output1
        float h = tanh_exp2(C_2LOG2E * o);
        __half hh = __float2half_rn(h);
        g_Ah[n] = *reinterpret_cast<unsigned short*>(&hh);
    }
}

// ---------------- kernel 5: GEMM partials = h2 @ w3 (fp16, deep cp.async) ---
// 8 stages, 7 chunk-groups in flight (~56KB/block); ONE block barrier per
// chunk; warp-local B conversion (padded rows, no bank conflicts).
#define GEMM_BN 128
#define GEMM_KRANGE (NN / GEMM_KSPLIT)   // 512
#define GEMM_NCHUNK (GEMM_KRANGE / 16)   // 32
#define NSTAGE 8
#define BF_LD 132    // floats per padded Bf row
#define BH_LD 136    // ushorts per padded Bh row

struct GemmSmem {
    unsigned short A[NSTAGE][MB][16];      // 16 KB (fp16, ldsm-ready)
    float Bf[NSTAGE][16][BF_LD];           // 66 KB (fp32 stages)
    unsigned short Bh[2][16][BH_LD];       // 8.5 KB (fp16 double buffer)
};
#define SMEM_GEMM_BYTES (sizeof(GemmSmem))

__device__ __forceinline__ void mma_f16(float c[4], const uint32_t a[4],
                                        const uint32_t b[2]) {
    asm volatile(
        "mma.sync.aligned.m16n8k16.row.col.f32.f16.f16.f32 "
        "{%0,%1,%2,%3}, {%4,%5,%6,%7}, {%8,%9}, {%0,%1,%2,%3};\n"
        : "+f"(c[0]), "+f"(c[1]), "+f"(c[2]), "+f"(c[3])
        : "r"(a[0]), "r"(a[1]), "r"(a[2]), "r"(a[3]), "r"(b[0]), "r"(b[1]));
}
__device__ __forceinline__ void ldsm_x4(uint32_t r[4], uint32_t addr) {
    asm volatile("ldmatrix.sync.aligned.m8n8.x4.shared.b16 {%0,%1,%2,%3}, [%4];"
                 : "=r"(r[0]), "=r"(r[1]), "=r"(r[2]), "=r"(r[3]) : "r"(addr));
}
__device__ __forceinline__ void ldsm_x2t(uint32_t r[2], uint32_t addr) {
    asm volatile("ldmatrix.sync.aligned.m8n8.x2.trans.shared.b16 {%0,%1}, [%2];"
                 : "=r"(r[0]), "=r"(r[1]) : "r"(addr));
}
__device__ __forceinline__ void cp16(uint32_t dst, const void* src) {
    asm volatile("cp.async.cg.shared.global [%0], [%1], 16;"
                 :: "r"(dst), "l"(src) : "memory");
}
__device__ __forceinline__ void cp_commit() {
    asm volatile("cp.async.commit_group;" ::: "memory");
}
__device__ __forceinline__ void cp_wait6() {
    asm volatile("cp.async.wait_group 6;" ::: "memory");
}

__global__ __launch_bounds__(256) void k_gemm(const float* __restrict__ w3) {
    extern __shared__ __align__(16) char smem_raw[];
    GemmSmem* S = reinterpret_cast<GemmSmem*>(smem_raw);

    int tid  = threadIdx.x;
    int warp = tid >> 5;
    int lane = tid & 31;
    int g    = lane >> 2;
    int tg   = lane & 3;
    int n0   = blockIdx.x * GEMM_BN;
    int kb   = blockIdx.y * GEMM_KRANGE;

    // cp.async staging coords
    int mA  = tid >> 1, cpA = (tid & 1) * 8;  // A: 128 threads x 16B
    int rB  = tid >> 5, seg = tid & 31;       // B: rows rB, rB+8; 16B segs

    float acc[4][2][4];
#pragma unroll
    for (int mi = 0; mi < 4; mi++)
#pragma unroll
        for (int ni = 0; ni < 2; ni++)
#pragma unroll
            for (int r = 0; r < 4; r++) acc[mi][ni][r] = 0.0f;

    // prologue: issue chunks 0..6
#pragma unroll
    for (int ck = 0; ck < NSTAGE - 1; ck++) {
        int k0 = kb + ck * 16;
        if (tid < 128)
            cp16((uint32_t)__cvta_generic_to_shared(&S->A[ck][mA][cpA]),
                 &g_Ah[mA * NN + k0 + cpA]);
        cp16((uint32_t)__cvta_generic_to_shared(&S->Bf[ck][rB][seg * 4]),
             &w3[(size_t)(k0 + rB) * NN + n0 + seg * 4]);
        cp16((uint32_t)__cvta_generic_to_shared(&S->Bf[ck][rB + 8][seg * 4]),
             &w3[(size_t)(k0 + rB + 8) * NN + n0 + seg * 4]);
        cp_commit();
    }

    uint32_t aA = (uint32_t)__cvta_generic_to_shared(
        &S->A[0][(lane & 15)][(lane >> 4) * 8]);
    uint32_t aB = (uint32_t)__cvta_generic_to_shared(
        &S->Bh[0][(lane & 15)][warp * 16]);
    const uint32_t strideAst = MB * 16 * 2;          // 2048
    const uint32_t strideBbuf = 16 * BH_LD * 2;      // bytes per Bh buffer

    // per-warp B conversion coords: rows lane>>1, col half (lane&1)*8
    int cvRow = lane >> 1;
    int cvCol = warp * 16 + (lane & 1) * 8;

#pragma unroll 1
    for (int ck = 0; ck < GEMM_NCHUNK; ck++) {
        int st = ck % NSTAGE;
        int p  = ck & 1;
        cp_wait6();             // chunk ck complete (6 newer groups pending)
        __syncthreads();        // A/Bf visible; prior reads of reused slots done

        // warp-local B convert: exactly the region this warp ldsm-reads
        {
            const float* sf = &S->Bf[st][cvRow][cvCol];
            float4 v0 = *reinterpret_cast<const float4*>(sf);
            float4 v1 = *reinterpret_cast<const float4*>(sf + 4);
            uint4 o;
            o.x = pack_f16x2(v0.x, v0.y);
            o.y = pack_f16x2(v0.z, v0.w);
            o.z = pack_f16x2(v1.x, v1.y);
            o.w = pack_f16x2(v1.z, v1.w);
            *reinterpret_cast<uint4*>(&S->Bh[p][cvRow][cvCol]) = o;
        }
        __syncwarp();

        uint32_t aH[4][4];
#pragma unroll
        for (int mi = 0; mi < 4; mi++)
            ldsm_x4(aH[mi], aA + st * strideAst + mi * 512);
        uint32_t bH[2][2];
#pragma unroll
        for (int ni = 0; ni < 2; ni++)
            ldsm_x2t(bH[ni], aB + p * strideBbuf + ni * 16);
#pragma unroll
        for (int mi = 0; mi < 4; mi++)
#pragma unroll
            for (int ni = 0; ni < 2; ni++)
                mma_f16(acc[mi][ni], aH[mi], bH[ni]);

        // issue chunk ck+7 into slot (ck+7)%8
        if (ck + NSTAGE - 1 < GEMM_NCHUNK) {
            int st2 = (ck + NSTAGE - 1) % NSTAGE;
            int k0 = kb + (ck + NSTAGE - 1) * 16;
            if (tid < 128)
                cp16((uint32_t)__cvta_generic_to_shared(&S->A[st2][mA][cpA]),
                     &g_Ah[mA * NN + k0 + cpA]);
            cp16((uint32_t)__cvta_generic_to_shared(&S->Bf[st2][rB][seg * 4]),
                 &w3[(size_t)(k0 + rB) * NN + n0 + seg * 4]);
            cp16((uint32_t)__cvta_generic_to_shared(&S->Bf[st2][rB + 8][seg * 4]),
                 &w3[(size_t)(k0 + rB + 8) * NN + n0 + seg * 4]);
        }
        cp_commit();   // uniform commit keeps wait_group arithmetic exact
    }

    // epilogue: plain v2 stores into this split's partial slab (no atomics)
    float* part = g_part + (size_t)blockIdx.y * N_TOTAL;
#pragma unroll
    for (int mi = 0; mi < 4; mi++) {
        int row = mi * 16 + g;
#pragma unroll
        for (int ni = 0; ni < 2; ni++) {
            int col = n0 + warp * 16 + ni * 8 + 2 * tg;
            *reinterpret_cast<float2*>(&part[(size_t)row * NN + col]) =
                make_float2(acc[mi][ni][0], acc[mi][ni][1]);
            *reinterpret_cast<float2*>(&part[(size_t)(row + 8) * NN + col]) =
                make_float2(acc[mi][ni][2], acc[mi][ni][3]);
        }
    }
}

// ---------------- kernel 6: reduce split-K partials + b3 --------------------
__global__ void k_red(const float* __restrict__ b3,
                      float* __restrict__ out2, int n4) {  // n4 = N_TOTAL/4
    int i = blockIdx.x * blockDim.x + threadIdx.x;
    if (i < n4) {
        float4 a = reinterpret_cast<const float4*>(b3)[i & (NN / 4 - 1)];
#pragma unroll
        for (int j = 0; j < GEMM_KSPLIT; j++) {
            float4 pv = reinterpret_cast<const float4*>(g_part)[(size_t)j * (N_TOTAL / 4) + i];
            a.x += pv.x; a.y += pv.y; a.z += pv.z; a.w += pv.w;
        }
        reinterpret_cast<float4*>(out2)[i] = a;
    }
}

// ---------------- launch ----------------------------------------------------
extern "C" void kernel_launch(void* const* d_in, const int* in_sizes, int n_in,
                              void* d_out, int out_size) {
    const float* feat = (const float*)d_in[0];
    const int*   src  = (const int*)d_in[1];
    const int*   dst  = (const int*)d_in[2];
    const float* ws1  = (const float*)d_in[3];
    const float* wn1  = (const float*)d_in[4];
    const float* b1   = (const float*)d_in[5];
    const float* ws2  = (const float*)d_in[6];
    const float* wn2  = (const float*)d_in[7];
    const float* b2   = (const float*)d_in[8];
    const float* w3   = (const float*)d_in[9];
    const float* b3   = (const float*)d_in[10];
    float* out = (float*)d_out;

    int N = in_sizes[0];   // 262144
    int E = in_sizes[1];   // 2097152

    cudaFuncSetAttribute(k_gemm, cudaFuncAttributeMaxDynamicSharedMemorySize,
                         (int)SMEM_GEMM_BYTES);

    // side stream: table build only (tiny; overlapped with zero+edge1)
    cudaStream_t s2;
    cudaStreamCreateWithFlags(&s2, cudaStreamNonBlocking);
    cudaEvent_t eF, eJ;
    cudaEventCreateWithFlags(&eF, cudaEventDisableTiming);
    cudaEventCreateWithFlags(&eJ, cudaEventDisableTiming);

    cudaEventRecord(eF, 0);
    cudaStreamWaitEvent(s2, eF, 0);
    k_tab<<<(TAB_N * TAB_N + 255) / 256, 256, 0, s2>>>(ws1, wn1, b1, ws2, wn2);
    cudaEventRecord(eJ, s2);

    k_zero<<<(N / 4 + 255) / 256, 256>>>(N / 4);
    k_edge1<<<(E / 4 + 255) / 256, 256>>>(feat, src, dst, E / 4);

    cudaStreamWaitEvent(0, eJ, 0);
    k_node1<<<(N + 255) / 256, 256>>>(feat, N);
    k_edge2<<<(E / 4 + 255) / 256, 256>>>(src, dst, E / 4);
    k_node2<<<(N + 255) / 256, 256>>>(b2, out, N);

    dim3 grid(NN / GEMM_BN, GEMM_KSPLIT);
    k_gemm<<<grid, 256, SMEM_GEMM_BYTES>>>(w3);
    k_red<<<(N / 4 + 255) / 256, 256>>>(b3, out + N, N / 4);
}